// round 11
// baseline (speedup 1.0000x reference)
#include <cuda_runtime.h>
#include <cuda_bf16.h>
#include <math.h>
#include <stdint.h>

// Problem constants
#define NN   50000
#define EE   800000
#define FIN  128
#define D1   256
#define NOUT 40
#define NTOT1 1024   // packed q|k|v|s layer 1 (4*256)
#define NTOT2 160    // packed q|k|v|s layer 2 (4*40)
#define N2P  256     // padded layer-2 N for GEMM tiles

// ---------------- static scratch ----------------
__device__ __align__(256) float g_p1[(size_t)NN * NTOT1];  // packed q1|k1|v1|s1
__device__ __align__(256) float g_p2[(size_t)NN * NTOT2];  // packed q2|k2|v2|s2

__device__ __align__(256) __nv_bfloat16 g_hhi[(size_t)NN * D1];
__device__ __align__(256) __nv_bfloat16 g_hlo[(size_t)NN * D1];
__device__ __align__(256) __nv_bfloat16 g_w1hi[NTOT1 * FIN];  // [n][k] transposed
__device__ __align__(256) __nv_bfloat16 g_w1lo[NTOT1 * FIN];
__device__ __align__(256) __nv_bfloat16 g_w2hi[N2P * D1];     // [n][k], rows >=160 zero
__device__ __align__(256) __nv_bfloat16 g_w2lo[N2P * D1];
__device__ __align__(256) float g_b1[NTOT1];
__device__ __align__(256) float g_b2[N2P];

__device__ __align__(256) int g_esrc[EE];
__device__ __align__(256) int g_edst[EE];
__device__ int g_is32;
__device__ int g_deg[NN];
__device__ __align__(256) int g_rowptr[NN + 1];
__device__ int g_wp[NN];
__device__ __align__(256) int g_csrsrc[EE];

static inline int cdiv(int a, int b) { return (a + b - 1) / b; }

// ---------------- init + edge dtype detect ----------------
__global__ void k_init(int n) {
    int i = blockIdx.x * blockDim.x + threadIdx.x;
    if (i == 0) g_is32 = 0;
    if (i < n) g_deg[i] = 0;
}
__global__ void k_detect(const int* __restrict__ w, int e) {
    int i = blockIdx.x * blockDim.x + threadIdx.x;
    if (i < e) { if (w[2 * i + 1] != 0) g_is32 = 1; }
}
// fused convert + degree histogram
__global__ void k_convhist(const void* __restrict__ ei, int e) {
    int i = blockIdx.x * blockDim.x + threadIdx.x;
    if (i >= e) return;
    int s_, d_;
    if (g_is32) {
        const int* p = (const int*)ei;
        s_ = p[i]; d_ = p[e + i];
    } else {
        const long long* p = (const long long*)ei;
        s_ = (int)p[i]; d_ = (int)p[e + i];
    }
    g_esrc[i] = s_;
    g_edst[i] = d_;
    atomicAdd(&g_deg[d_], 1);
}

// ---------------- CSR: warp-shfl scan + scatter ----------------
__global__ void k_scan(int n) {   // single block, 1024 threads
    __shared__ int wsum[32];
    const int tid = threadIdx.x, lane = tid & 31, wid = tid >> 5;
    int carry = 0;
    for (int base = 0; base <= n; base += 1024) {
        int idx = base + tid;
        int v = (idx < n) ? g_deg[idx] : 0;
        int x = v;
        #pragma unroll
        for (int o = 1; o < 32; o <<= 1) {
            int t = __shfl_up_sync(0xffffffffu, x, o);
            if (lane >= o) x += t;
        }
        if (lane == 31) wsum[wid] = x;
        __syncthreads();
        if (wid == 0) {
            int w = wsum[lane];
            #pragma unroll
            for (int o = 1; o < 32; o <<= 1) {
                int t = __shfl_up_sync(0xffffffffu, w, o);
                if (lane >= o) w += t;
            }
            wsum[lane] = w;
        }
        __syncthreads();
        int pre = wid ? wsum[wid - 1] : 0;
        int excl = carry + pre + x - v;
        if (idx <= n) {
            g_rowptr[idx] = excl;
            if (idx < n) g_wp[idx] = excl;
        }
        carry += wsum[31];
        __syncthreads();
    }
}
__global__ void k_scatter(int e) {
    int i = blockIdx.x * blockDim.x + threadIdx.x;
    if (i < e) {
        int pos = atomicAdd(&g_wp[g_edst[i]], 1);
        g_csrsrc[pos] = g_esrc[i];
    }
}

// ---------------- weight packing ----------------
__global__ void k_packw(
    const float* q1w, const float* k1w, const float* v1w, const float* s1w,
    const float* q1b, const float* k1b, const float* v1b, const float* s1b,
    const float* q2w, const float* k2w, const float* v2w, const float* s2w,
    const float* q2b, const float* k2b, const float* v2b, const float* s2b)
{
    const float SC1 = 0.17677669529663687f;   // 1/sqrt(32)
    const float SC2 = 0.15811388300841897f;   // 1/sqrt(40)
    int i = blockIdx.x * blockDim.x + threadIdx.x;
    const int W1 = NTOT1 * FIN, W2 = N2P * D1;
    if (i < W1) {
        int n = i / FIN, k = i % FIN;
        const float* s = (n < 256) ? q1w : (n < 512) ? k1w : (n < 768) ? v1w : s1w;
        float v = s[k * 256 + (n & 255)];
        if (n < 256) v *= SC1;
        __nv_bfloat16 h = __float2bfloat16(v);
        g_w1hi[i] = h;
        g_w1lo[i] = __float2bfloat16(v - __bfloat162float(h));
    } else if (i < W1 + W2) {
        int j = i - W1;
        int n = j / D1, k = j % D1;
        float v = 0.f;
        if (n < NTOT2) {
            const float* s = (n < 40) ? q2w : (n < 80) ? k2w : (n < 120) ? v2w : s2w;
            v = s[k * 40 + (n % 40)];
            if (n < 40) v *= SC2;
        }
        __nv_bfloat16 h = __float2bfloat16(v);
        g_w2hi[j] = h;
        g_w2lo[j] = __float2bfloat16(v - __bfloat162float(h));
    } else if (i < W1 + W2 + NTOT1) {
        int c = i - W1 - W2;
        const float* s = (c < 256) ? q1b : (c < 512) ? k1b : (c < 768) ? v1b : s1b;
        float v = s[c & 255];
        if (c < 256) v *= SC1;
        g_b1[c] = v;
    } else if (i < W1 + W2 + NTOT1 + N2P) {
        int c = i - W1 - W2 - NTOT1;
        float v = 0.f;
        if (c < NTOT2) {
            const float* s = (c < 40) ? q2b : (c < 80) ? k2b : (c < 120) ? v2b : s2b;
            v = s[c % 40];
            if (c < 40) v *= SC2;
        }
        g_b2[c] = v;
    }
}

// ---------------- mma.sync bf16 split GEMM ----------------
__device__ __forceinline__ void mma16816(float* c, const uint32_t* a, const uint32_t* b) {
    asm volatile(
        "mma.sync.aligned.m16n8k16.row.col.f32.bf16.bf16.f32 "
        "{%0,%1,%2,%3}, {%4,%5,%6,%7}, {%8,%9}, {%0,%1,%2,%3};\n"
        : "+f"(c[0]), "+f"(c[1]), "+f"(c[2]), "+f"(c[3])
        : "r"(a[0]), "r"(a[1]), "r"(a[2]), "r"(a[3]), "r"(b[0]), "r"(b[1]));
}
#define LDSM4(r, addr) \
    asm volatile("ldmatrix.sync.aligned.m8n8.x4.shared.b16 {%0,%1,%2,%3}, [%4];" \
        : "=r"((r)[0]), "=r"((r)[1]), "=r"((r)[2]), "=r"((r)[3]) : "r"(addr))
#define CPASYNC16(saddr, gptr) \
    asm volatile("cp.async.cg.shared.global [%0], [%1], 16;" :: "r"(saddr), "l"(gptr))
#define CPASYNC_COMMIT() asm volatile("cp.async.commit_group;" ::: "memory")
#define CPASYNC_WAIT0()  asm volatile("cp.async.wait_group 0;" ::: "memory")
#define CPASYNC_WAIT1()  asm volatile("cp.async.wait_group 1;" ::: "memory")

__device__ __forceinline__ uint32_t smem_u32(const void* p) {
    uint32_t a;
    asm("{ .reg .u64 t; cvta.to.shared.u64 t, %1; cvt.u32.u64 %0, t; }" : "=r"(a) : "l"(p));
    return a;
}

#define SMSTR 72     // bf16 row stride (64 data + 8 pad); 144B row, 16B aligned
#define TILEB (128 * SMSTR)

// C[M,*] = A[M,K] @ B^T[N,K] + bias ; 3-term split-bf16 in ONE k-pass.
// 2-stage cp.async pipeline on B (B(kc+1) in flight during A-stage + compute of kc).
// SMEM: AsH | AsL | BH0 | BH1 | BL0 | BL1  = 6*TILEB bf16 = 110.6 KB (2 CTA/SM).
template <int KCHUNKS, bool AF32>
__global__ void __launch_bounds__(256, 2) k_mma2(
    const void* __restrict__ Ahi_, const void* __restrict__ Alo_,
    const __nv_bfloat16* __restrict__ Bhi, const __nv_bfloat16* __restrict__ Blo,
    const float* __restrict__ bias, float* __restrict__ C,
    int M, int Nvalid, int ldc)
{
    constexpr int K = KCHUNKS * 64;
    extern __shared__ __nv_bfloat16 smem[];
    __nv_bfloat16* AsH = smem;
    __nv_bfloat16* AsL = smem + TILEB;

    const int tid = threadIdx.x, lane = tid & 31, wid = tid >> 5;
    const int wm = wid & 1, wn = wid >> 1;      // warps 2(M) x 4(N); warp tile 64x32
    const int grp = lane >> 2, thr = lane & 3;
    const int sub = lane >> 3, lr = lane & 7;
    const int m0 = blockIdx.y * 128, n0 = blockIdx.x * 128;

    const uint32_t sAH = smem_u32(smem);
    const uint32_t sAL = sAH + TILEB * 2;
    const uint32_t sBH0 = sAH + 2 * TILEB * 2;   // +(kc&1)*TILEB*2
    const uint32_t sBL0 = sAH + 4 * TILEB * 2;
    const int rA = wm * 64 + lr + (sub & 1) * 8;
    const int kA = (sub >> 1) * 8;
    const int rB = wn * 32 + (sub >> 1) * 8 + lr;
    const int kB = (sub & 1) * 8;
    const bool active = (n0 + wn * 32) < Nvalid;

    float c[4][4][4];
    #pragma unroll
    for (int mt = 0; mt < 4; mt++)
        #pragma unroll
        for (int nt = 0; nt < 4; nt++)
            #pragma unroll
            for (int r = 0; r < 4; r++) c[mt][nt][r] = 0.f;

    // prologue: B(0) -> buffer 0
    #pragma unroll
    for (int i = 0; i < 4; i++) {
        int q = tid + i * 256;
        int r = q >> 3, s = q & 7;
        uint32_t so = (uint32_t)(r * SMSTR + s * 8) * 2;
        CPASYNC16(sBH0 + so, &Bhi[(size_t)(n0 + r) * K + s * 8]);
        CPASYNC16(sBL0 + so, &Blo[(size_t)(n0 + r) * K + s * 8]);
    }
    CPASYNC_COMMIT();

    #pragma unroll
    for (int kc = 0; kc < KCHUNKS; kc++) {
        const int kk = kc * 64;
        const uint32_t bufc = (uint32_t)((kc & 1) * TILEB * 2);
        const uint32_t bufn = (uint32_t)(((kc + 1) & 1) * TILEB * 2);

        // A stage (cp.async path first so its group precedes B(kc+1))
        if (!AF32) {
            const __nv_bfloat16* Ahi = (const __nv_bfloat16*)Ahi_;
            const __nv_bfloat16* Alo = (const __nv_bfloat16*)Alo_;
            #pragma unroll
            for (int i = 0; i < 4; i++) {
                int q = tid + i * 256;
                int r = q >> 3, s = q & 7;
                int grow = m0 + r;
                uint32_t so = (uint32_t)(r * SMSTR + s * 8) * 2;
                if (grow < M) {
                    CPASYNC16(sAH + so, &Ahi[(size_t)grow * K + kk + s * 8]);
                    CPASYNC16(sAL + so, &Alo[(size_t)grow * K + kk + s * 8]);
                } else {
                    *(uint4*)&AsH[r * SMSTR + s * 8] = make_uint4(0u, 0u, 0u, 0u);
                    *(uint4*)&AsL[r * SMSTR + s * 8] = make_uint4(0u, 0u, 0u, 0u);
                }
            }
            CPASYNC_COMMIT();
        }
        // issue B(kc+1) into the other buffer
        if (kc + 1 < KCHUNKS) {
            const int kk2 = (kc + 1) * 64;
            #pragma unroll
            for (int i = 0; i < 4; i++) {
                int q = tid + i * 256;
                int r = q >> 3, s = q & 7;
                uint32_t so = (uint32_t)(r * SMSTR + s * 8) * 2;
                CPASYNC16(sBH0 + bufn + so, &Bhi[(size_t)(n0 + r) * K + kk2 + s * 8]);
                CPASYNC16(sBL0 + bufn + so, &Blo[(size_t)(n0 + r) * K + kk2 + s * 8]);
            }
            CPASYNC_COMMIT();
        }
        // A fp32 -> hi/lo convert (overlaps the B(kc+1) copy)
        if (AF32) {
            const float* A32 = (const float*)Ahi_;
            #pragma unroll
            for (int i = 0; i < 4; i++) {
                int q = tid + i * 256;
                int r = q >> 3, s = q & 7;
                int grow = m0 + r;
                float4 a0 = make_float4(0.f, 0.f, 0.f, 0.f), a1 = a0;
                if (grow < M) {
                    a0 = *(const float4*)&A32[(size_t)grow * K + kk + s * 8];
                    a1 = *(const float4*)&A32[(size_t)grow * K + kk + s * 8 + 4];
                }
                float vv[8] = { a0.x, a0.y, a0.z, a0.w, a1.x, a1.y, a1.z, a1.w };
                __nv_bfloat162 ph[4], pl[4];
                #pragma unroll
                for (int j = 0; j < 4; j++) {
                    __nv_bfloat16 h0 = __float2bfloat16(vv[2*j]);
                    __nv_bfloat16 h1 = __float2bfloat16(vv[2*j+1]);
                    ph[j] = __halves2bfloat162(h0, h1);
                    pl[j] = __halves2bfloat162(
                        __float2bfloat16(vv[2*j]   - __bfloat162float(h0)),
                        __float2bfloat16(vv[2*j+1] - __bfloat162float(h1)));
                }
                *(uint4*)&AsH[r * SMSTR + s * 8] = *(uint4*)ph;
                *(uint4*)&AsL[r * SMSTR + s * 8] = *(uint4*)pl;
            }
        }
        // wait: B(kc) [+ A(kc) if cp.async] complete; B(kc+1) may stay in flight
        if (kc + 1 < KCHUNKS) { CPASYNC_WAIT1(); } else { CPASYNC_WAIT0(); }
        __syncthreads();

        if (active) {
            const uint32_t bH = sBH0 + bufc, bL = sBL0 + bufc;
            #pragma unroll
            for (int ks = 0; ks < 4; ks++) {
                const int kb = ks * 16;
                uint32_t ah[4][4], bh[2][4], t[2][4], al4[4];
                #pragma unroll
                for (int mt = 0; mt < 4; mt++)
                    LDSM4(ah[mt], sAH + ((rA + mt * 16) * SMSTR + kb + kA) * 2);
                #pragma unroll
                for (int p = 0; p < 2; p++)
                    LDSM4(bh[p], bH + ((rB + p * 16) * SMSTR + kb + kB) * 2);
                #pragma unroll
                for (int mt = 0; mt < 4; mt++)
                    #pragma unroll
                    for (int p = 0; p < 2; p++) {
                        mma16816(c[mt][2 * p],     ah[mt], &bh[p][0]);
                        mma16816(c[mt][2 * p + 1], ah[mt], &bh[p][2]);
                    }
                #pragma unroll
                for (int p = 0; p < 2; p++)
                    LDSM4(t[p], bL + ((rB + p * 16) * SMSTR + kb + kB) * 2);
                #pragma unroll
                for (int mt = 0; mt < 4; mt++)
                    #pragma unroll
                    for (int p = 0; p < 2; p++) {
                        mma16816(c[mt][2 * p],     ah[mt], &t[p][0]);
                        mma16816(c[mt][2 * p + 1], ah[mt], &t[p][2]);
                    }
                #pragma unroll
                for (int mt = 0; mt < 4; mt++) {
                    LDSM4(al4, sAL + ((rA + mt * 16) * SMSTR + kb + kA) * 2);
                    #pragma unroll
                    for (int p = 0; p < 2; p++) {
                        mma16816(c[mt][2 * p],     al4, &bh[p][0]);
                        mma16816(c[mt][2 * p + 1], al4, &bh[p][2]);
                    }
                }
            }
        }
        __syncthreads();
    }

    #pragma unroll
    for (int mt = 0; mt < 4; mt++) {
        int row = m0 + wm * 64 + mt * 16 + grp;
        #pragma unroll
        for (int nt = 0; nt < 4; nt++) {
            int col = n0 + wn * 32 + nt * 8 + thr * 2;
            if (col >= Nvalid) continue;
            float b0 = bias[col], b1 = bias[col + 1];
            if (row < M)
                *(float2*)&C[(size_t)row * ldc + col] =
                    make_float2(c[mt][nt][0] + b0, c[mt][nt][1] + b1);
            if (row + 8 < M)
                *(float2*)&C[(size_t)(row + 8) * ldc + col] =
                    make_float2(c[mt][nt][2] + b0, c[mt][nt][3] + b1);
        }
    }
}

// ---------------- fused layer-1 edge pass (x2 unroll; streaming hints) ----------------
// q/s/h/csrsrc are streamed exactly once -> evict-first (__ldcs/__stcs) keeps L2
// free for the 102MB k|v gather set (which then nearly fits in 126MB L2).
__global__ void __launch_bounds__(256) k_edge1(const float* __restrict__ bw, int n)
{
    __shared__ float w[3 * D1];
    for (int i = threadIdx.x; i < 3 * D1; i += blockDim.x) w[i] = bw[i];
    __syncthreads();

    int warp = (blockIdx.x * blockDim.x + threadIdx.x) >> 5;
    int lane = threadIdx.x & 31;
    if (warp >= n) return;
    int s0 = g_rowptr[warp], s1 = g_rowptr[warp + 1];

    const float* prow = g_p1 + (size_t)warp * NTOT1;
    float4 qa = __ldcs((const float4*)(prow + lane * 8));
    float4 qb = __ldcs((const float4*)(prow + lane * 8 + 4));

    float a0x=0,a0y=0,a0z=0,a0w=0, a1x=0,a1y=0,a1z=0,a1w=0;
    float asum = 0.f;
    int s = s0;
    for (; s + 1 < s1; s += 2) {
        int src0 = __ldcs(&g_csrsrc[s]), src1 = __ldcs(&g_csrsrc[s + 1]);
        const float* b0p = g_p1 + (size_t)src0 * NTOT1;
        const float* b1p = g_p1 + (size_t)src1 * NTOT1;
        float4 ka0 = *(const float4*)(b0p + 256 + lane * 8);
        float4 kb0 = *(const float4*)(b0p + 256 + lane * 8 + 4);
        float4 ka1 = *(const float4*)(b1p + 256 + lane * 8);
        float4 kb1 = *(const float4*)(b1p + 256 + lane * 8 + 4);
        float4 v00 = *(const float4*)(b0p + 512 + lane * 8);
        float4 v01 = *(const float4*)(b0p + 512 + lane * 8 + 4);
        float4 v10 = *(const float4*)(b1p + 512 + lane * 8);
        float4 v11 = *(const float4*)(b1p + 512 + lane * 8 + 4);

        float p0 = qa.x*ka0.x + qa.y*ka0.y + qa.z*ka0.z + qa.w*ka0.w
                 + qb.x*kb0.x + qb.y*kb0.y + qb.z*kb0.z + qb.w*kb0.w;
        float p1 = qa.x*ka1.x + qa.y*ka1.y + qa.z*ka1.z + qa.w*ka1.w
                 + qb.x*kb1.x + qb.y*kb1.y + qb.z*kb1.z + qb.w*kb1.w;
        p0 += __shfl_xor_sync(0xffffffffu, p0, 1);
        p0 += __shfl_xor_sync(0xffffffffu, p0, 2);
        p1 += __shfl_xor_sync(0xffffffffu, p1, 1);
        p1 += __shfl_xor_sync(0xffffffffu, p1, 2);
        float e0 = expf(p0), e1 = expf(p1);   // q pre-scaled by 1/sqrt(32)
        asum += e0 + e1;
        a0x = fmaf(e0, v00.x, a0x); a0y = fmaf(e0, v00.y, a0y);
        a0z = fmaf(e0, v00.z, a0z); a0w = fmaf(e0, v00.w, a0w);
        a1x = fmaf(e0, v01.x, a1x); a1y = fmaf(e0, v01.y, a1y);
        a1z = fmaf(e0, v01.z, a1z); a1w = fmaf(e0, v01.w, a1w);
        a0x = fmaf(e1, v10.x, a0x); a0y = fmaf(e1, v10.y, a0y);
        a0z = fmaf(e1, v10.z, a0z); a0w = fmaf(e1, v10.w, a0w);
        a1x = fmaf(e1, v11.x, a1x); a1y = fmaf(e1, v11.y, a1y);
        a1z = fmaf(e1, v11.z, a1z); a1w = fmaf(e1, v11.w, a1w);
    }
    if (s < s1) {
        int src = __ldcs(&g_csrsrc[s]);
        const float* base = g_p1 + (size_t)src * NTOT1;
        float4 ka = *(const float4*)(base + 256 + lane * 8);
        float4 kb = *(const float4*)(base + 256 + lane * 8 + 4);
        float4 v0 = *(const float4*)(base + 512 + lane * 8);
        float4 v1 = *(const float4*)(base + 512 + lane * 8 + 4);
        float p = qa.x*ka.x + qa.y*ka.y + qa.z*ka.z + qa.w*ka.w
                + qb.x*kb.x + qb.y*kb.y + qb.z*kb.z + qb.w*kb.w;
        p += __shfl_xor_sync(0xffffffffu, p, 1);
        p += __shfl_xor_sync(0xffffffffu, p, 2);
        float e = expf(p);
        asum += e;
        a0x = fmaf(e, v0.x, a0x); a0y = fmaf(e, v0.y, a0y);
        a0z = fmaf(e, v0.z, a0z); a0w = fmaf(e, v0.w, a0w);
        a1x = fmaf(e, v1.x, a1x); a1y = fmaf(e, v1.y, a1y);
        a1z = fmaf(e, v1.z, a1z); a1w = fmaf(e, v1.w, a1w);
    }
    float inv = (s1 > s0) ? 1.0f / asum : 0.f;
    float o[8] = { a0x*inv, a0y*inv, a0z*inv, a0w*inv, a1x*inv, a1y*inv, a1z*inv, a1w*inv };

    float4 sa = __ldcs((const float4*)(prow + 768 + lane * 8));
    float4 sbv = __ldcs((const float4*)(prow + 768 + lane * 8 + 4));
    float sk[8] = { sa.x, sa.y, sa.z, sa.w, sbv.x, sbv.y, sbv.z, sbv.w };

    float g = 0.f;
    #pragma unroll
    for (int j = 0; j < 8; j++) {
        int ccol = lane * 8 + j;
        g += o[j] * w[ccol] + sk[j] * w[D1 + ccol] + (o[j] - sk[j]) * w[2 * D1 + ccol];
    }
    #pragma unroll
    for (int off = 16; off >= 1; off >>= 1) g += __shfl_xor_sync(0xffffffffu, g, off);
    float beta = 1.0f / (1.0f + expf(-g));

    __nv_bfloat162 ph[4], pl[4];
    #pragma unroll
    for (int j = 0; j < 4; j++) {
        float v0 = beta * sk[2*j]   + (1.0f - beta) * o[2*j];
        float v1 = beta * sk[2*j+1] + (1.0f - beta) * o[2*j+1];
        v0 = (v0 > 0.f) ? v0 : (expf(v0) - 1.0f);   // ELU
        v1 = (v1 > 0.f) ? v1 : (expf(v1) - 1.0f);
        __nv_bfloat16 h0 = __float2bfloat16(v0), h1 = __float2bfloat16(v1);
        ph[j] = __halves2bfloat162(h0, h1);
        pl[j] = __halves2bfloat162(__float2bfloat16(v0 - __bfloat162float(h0)),
                                   __float2bfloat16(v1 - __bfloat162float(h1)));
    }
    __stcs((uint4*)&g_hhi[(size_t)warp * D1 + lane * 8], *(uint4*)ph);
    __stcs((uint4*)&g_hlo[(size_t)warp * D1 + lane * 8], *(uint4*)pl);
}

// ---------------- fused layer-2 edge pass (unrolled x2 gather) ----------------
__global__ void __launch_bounds__(256) k_edge2(const float* __restrict__ bw,
                                               float* __restrict__ out, int n)
{
    __shared__ float w[3 * NOUT];
    for (int i = threadIdx.x; i < 3 * NOUT; i += blockDim.x) w[i] = bw[i];
    __syncthreads();

    int warp = (blockIdx.x * blockDim.x + threadIdx.x) >> 5;
    int lane = threadIdx.x & 31;
    if (warp >= n) return;
    int s0 = g_rowptr[warp], s1 = g_rowptr[warp + 1];

    const float* prow = g_p2 + (size_t)warp * NTOT2;
    float q0 = 0.f, q1 = 0.f;
    if (lane < 20) {
        float2 qq = *(const float2*)(prow + lane * 2);
        q0 = qq.x; q1 = qq.y;
    }
    float acc0 = 0.f, acc1 = 0.f, asum = 0.f;
    int s = s0;
    for (; s + 1 < s1; s += 2) {
        int src0 = __ldcs(&g_csrsrc[s]), src1 = __ldcs(&g_csrsrc[s + 1]);
        const float* b0p = g_p2 + (size_t)src0 * NTOT2;
        const float* b1p = g_p2 + (size_t)src1 * NTOT2;
        float p0 = 0.f, p1 = 0.f;
        float v00 = 0.f, v01 = 0.f, v10 = 0.f, v11 = 0.f;
        if (lane < 20) {
            float2 k0 = *(const float2*)(b0p + 40 + lane * 2);
            float2 k1 = *(const float2*)(b1p + 40 + lane * 2);
            float2 w0 = *(const float2*)(b0p + 80 + lane * 2);
            float2 w1 = *(const float2*)(b1p + 80 + lane * 2);
            p0 = q0 * k0.x + q1 * k0.y;
            p1 = q0 * k1.x + q1 * k1.y;
            v00 = w0.x; v01 = w0.y; v10 = w1.x; v11 = w1.y;
        }
        #pragma unroll
        for (int off = 16; off >= 1; off >>= 1) {
            p0 += __shfl_xor_sync(0xffffffffu, p0, off);
            p1 += __shfl_xor_sync(0xffffffffu, p1, off);
        }
        float e0 = expf(p0), e1 = expf(p1);   // q pre-scaled by 1/sqrt(40)
        asum += e0 + e1;
        acc0 = fmaf(e0, v00, acc0); acc1 = fmaf(e0, v01, acc1);
        acc0 = fmaf(e1, v10, acc0); acc1 = fmaf(e1, v11, acc1);
    }
    if (s < s1) {
        int src = __ldcs(&g_csrsrc[s]);
        const float* base = g_p2 + (size_t)src * NTOT2;
        float p = 0.f, v0 = 0.f, v1 = 0.f;
        if (lane < 20) {
            float2 kk = *(const float2*)(base + 40 + lane * 2);
            p = q0 * kk.x + q1 * kk.y;
            float2 vv = *(const float2*)(base + 80 + lane * 2);
            v0 = vv.x; v1 = vv.y;
        }
        #pragma unroll
        for (int off = 16; off >= 1; off >>= 1) p += __shfl_xor_sync(0xffffffffu, p, off);
        float e = expf(p);
        asum += e;
        acc0 = fmaf(e, v0, acc0);
        acc1 = fmaf(e, v1, acc1);
    }
    float inv = (s1 > s0) ? 1.0f / asum : 0.f;
    float o0 = acc0 * inv, o1 = acc1 * inv;

    float sk0 = 0.f, sk1 = 0.f, g = 0.f;
    if (lane < 20) {
        float2 ss = *(const float2*)(prow + 120 + lane * 2);
        sk0 = ss.x; sk1 = ss.y;
        int ccol = lane * 2;
        g = o0 * w[ccol]     + sk0 * w[NOUT + ccol]     + (o0 - sk0) * w[2 * NOUT + ccol]
          + o1 * w[ccol + 1] + sk1 * w[NOUT + ccol + 1] + (o1 - sk1) * w[2 * NOUT + ccol + 1];
    }
    #pragma unroll
    for (int off = 16; off >= 1; off >>= 1) g += __shfl_xor_sync(0xffffffffu, g, off);
    float beta = 1.0f / (1.0f + expf(-g));
    if (lane < 20) {
        float r0 = beta * sk0 + (1.0f - beta) * o0;
        float r1 = beta * sk1 + (1.0f - beta) * o1;
        *(float2*)(out + (size_t)warp * NOUT + lane * 2) = make_float2(r0, r1);
    }
}

// ---------------- launch ----------------
extern "C" void kernel_launch(void* const* d_in, const int* in_sizes, int n_in,
                              void* d_out, int out_size)
{
    const float* x = (const float*)d_in[0];
    const void* ei = d_in[1];
    const float* q1w = (const float*)d_in[2];
    const float* q1b = (const float*)d_in[3];
    const float* k1w = (const float*)d_in[4];
    const float* k1b = (const float*)d_in[5];
    const float* v1w = (const float*)d_in[6];
    const float* v1b = (const float*)d_in[7];
    const float* s1w = (const float*)d_in[8];
    const float* s1b = (const float*)d_in[9];
    const float* b1w = (const float*)d_in[10];
    const float* q2w = (const float*)d_in[11];
    const float* q2b = (const float*)d_in[12];
    const float* k2w = (const float*)d_in[13];
    const float* k2b = (const float*)d_in[14];
    const float* v2w = (const float*)d_in[15];
    const float* v2b = (const float*)d_in[16];
    const float* s2w = (const float*)d_in[17];
    const float* s2b = (const float*)d_in[18];
    const float* b2w = (const float*)d_in[19];
    float* out = (float*)d_out;

    const int n = in_sizes[0] / FIN;   // 50000
    const int e = in_sizes[1] / 2;     // 800000

    float* d_p1; cudaGetSymbolAddress((void**)&d_p1, g_p1);
    float* d_p2; cudaGetSymbolAddress((void**)&d_p2, g_p2);
    __nv_bfloat16 *d_hhi, *d_hlo, *d_w1hi, *d_w1lo, *d_w2hi, *d_w2lo;
    cudaGetSymbolAddress((void**)&d_hhi, g_hhi);
    cudaGetSymbolAddress((void**)&d_hlo, g_hlo);
    cudaGetSymbolAddress((void**)&d_w1hi, g_w1hi);
    cudaGetSymbolAddress((void**)&d_w1lo, g_w1lo);
    cudaGetSymbolAddress((void**)&d_w2hi, g_w2hi);
    cudaGetSymbolAddress((void**)&d_w2lo, g_w2lo);
    float *d_b1, *d_b2;
    cudaGetSymbolAddress((void**)&d_b1, g_b1);
    cudaGetSymbolAddress((void**)&d_b2, g_b2);

    static cudaStream_t s2 = 0;
    static cudaEvent_t evA = 0, evB = 0;
    if (!s2)  cudaStreamCreateWithFlags(&s2, cudaStreamNonBlocking);
    if (!evA) cudaEventCreateWithFlags(&evA, cudaEventDisableTiming);
    if (!evB) cudaEventCreateWithFlags(&evB, cudaEventDisableTiming);

    const int GSMEM = 6 * TILEB * 2;  // 110592 B (2 CTA/SM: 221KB < 228KB)
    cudaFuncSetAttribute((const void*)k_mma2<2, true>,  cudaFuncAttributeMaxDynamicSharedMemorySize, GSMEM);
    cudaFuncSetAttribute((const void*)k_mma2<4, false>, cudaFuncAttributeMaxDynamicSharedMemorySize, GSMEM);

    const int mblocks = cdiv(n, 128);
    const int nodeBlocks = cdiv(n * 32, 256);

    // fork immediately: CSR chain (no deps on main-stream work)
    cudaEventRecord(evA, 0);
    cudaStreamWaitEvent(s2, evA, 0);

    k_init<<<cdiv(n, 256), 256, 0, s2>>>(n);                       // #1
    k_detect<<<cdiv(e, 256), 256, 0, s2>>>((const int*)ei, e);     // #2
    const int packTotal = NTOT1 * FIN + N2P * D1 + NTOT1 + N2P;
    k_packw<<<cdiv(packTotal, 256), 256>>>(                        // #3 (main)
        q1w, k1w, v1w, s1w, q1b, k1b, v1b, s1b,
        q2w, k2w, v2w, s2w, q2b, k2b, v2b, s2b);
    k_mma2<2, true><<<dim3(NTOT1 / 128, mblocks), 256, GSMEM>>>(   // #4 (main)
        x, nullptr, d_w1hi, d_w1lo, d_b1, d_p1, n, NTOT1, NTOT1);

    k_convhist<<<cdiv(e, 256), 256, 0, s2>>>(ei, e);               // #5
    k_scan<<<1, 1024, 0, s2>>>(n);                                 // #6
    k_scatter<<<cdiv(e, 256), 256, 0, s2>>>(e);                    // #7
    cudaEventRecord(evB, s2);

    // join: edge1 needs gemm1 (main) + CSR (s2)
    cudaStreamWaitEvent(0, evB, 0);
    k_edge1<<<nodeBlocks, 256>>>(b1w, n);

    // ---- layer 2 ----
    k_mma2<4, false><<<dim3(N2P / 128, mblocks), 256, GSMEM>>>(
        d_hhi, d_hlo, d_w2hi, d_w2lo, d_b2, d_p2, n, NTOT2, NTOT2);
    k_edge2<<<nodeBlocks, 256>>>(b2w, out, n);
}

// round 12
// speedup vs baseline: 1.5865x; 1.5865x over previous
#include <cuda_runtime.h>
#include <cuda_bf16.h>
#include <math.h>
#include <stdint.h>

// Problem constants
#define NN   50000
#define EE   800000
#define FIN  128
#define D1   256
#define NOUT 40
#define NTOT1 1024   // packed q|k|v|s layer 1 (4*256)
#define NTOT2 160    // packed q|k|v|s layer 2 (4*40)
#define N2P  256     // padded layer-2 N for GEMM tiles

// ---------------- static scratch ----------------
__device__ __align__(256) float g_p1[(size_t)NN * NTOT1];  // packed q1|k1|v1|s1
__device__ __align__(256) float g_p2[(size_t)NN * NTOT2];  // packed q2|k2|v2|s2

__device__ __align__(256) __nv_bfloat16 g_xhi[(size_t)NN * FIN];
__device__ __align__(256) __nv_bfloat16 g_xlo[(size_t)NN * FIN];
__device__ __align__(256) __nv_bfloat16 g_hhi[(size_t)NN * D1];
__device__ __align__(256) __nv_bfloat16 g_hlo[(size_t)NN * D1];
__device__ __align__(256) __nv_bfloat16 g_w1hi[NTOT1 * FIN];  // [n][k] transposed
__device__ __align__(256) __nv_bfloat16 g_w1lo[NTOT1 * FIN];
__device__ __align__(256) __nv_bfloat16 g_w2hi[N2P * D1];     // [n][k], rows >=160 zero
__device__ __align__(256) __nv_bfloat16 g_w2lo[N2P * D1];
__device__ __align__(256) float g_b1[NTOT1];
__device__ __align__(256) float g_b2[N2P];

__device__ __align__(256) int g_esrc[EE];
__device__ __align__(256) int g_edst[EE];
__device__ int g_is32;
__device__ int g_deg[NN];
__device__ __align__(256) int g_rowptr[NN + 1];
__device__ int g_wp[NN];
__device__ __align__(256) int g_csrsrc[EE];

static inline int cdiv(int a, int b) { return (a + b - 1) / b; }

// ---------------- init + edge dtype detect ----------------
__global__ void k_init(int n) {
    int i = blockIdx.x * blockDim.x + threadIdx.x;
    if (i == 0) g_is32 = 0;
    if (i < n) g_deg[i] = 0;
}
__global__ void k_detect(const int* __restrict__ w, int e) {
    int i = blockIdx.x * blockDim.x + threadIdx.x;
    if (i < e) { if (w[2 * i + 1] != 0) g_is32 = 1; }
}
// fused convert + degree histogram
__global__ void k_convhist(const void* __restrict__ ei, int e) {
    int i = blockIdx.x * blockDim.x + threadIdx.x;
    if (i >= e) return;
    int s_, d_;
    if (g_is32) {
        const int* p = (const int*)ei;
        s_ = p[i]; d_ = p[e + i];
    } else {
        const long long* p = (const long long*)ei;
        s_ = (int)p[i]; d_ = (int)p[e + i];
    }
    g_esrc[i] = s_;
    g_edst[i] = d_;
    atomicAdd(&g_deg[d_], 1);
}

// ---------------- CSR: warp-shfl scan + scatter ----------------
__global__ void k_scan(int n) {   // single block, 1024 threads
    __shared__ int wsum[32];
    const int tid = threadIdx.x, lane = tid & 31, wid = tid >> 5;
    int carry = 0;
    for (int base = 0; base <= n; base += 1024) {
        int idx = base + tid;
        int v = (idx < n) ? g_deg[idx] : 0;
        int x = v;
        #pragma unroll
        for (int o = 1; o < 32; o <<= 1) {
            int t = __shfl_up_sync(0xffffffffu, x, o);
            if (lane >= o) x += t;
        }
        if (lane == 31) wsum[wid] = x;
        __syncthreads();
        if (wid == 0) {
            int w = wsum[lane];
            #pragma unroll
            for (int o = 1; o < 32; o <<= 1) {
                int t = __shfl_up_sync(0xffffffffu, w, o);
                if (lane >= o) w += t;
            }
            wsum[lane] = w;
        }
        __syncthreads();
        int pre = wid ? wsum[wid - 1] : 0;
        int excl = carry + pre + x - v;
        if (idx <= n) {
            g_rowptr[idx] = excl;
            if (idx < n) g_wp[idx] = excl;
        }
        carry += wsum[31];
        __syncthreads();
    }
}
__global__ void k_scatter(int e) {
    int i = blockIdx.x * blockDim.x + threadIdx.x;
    if (i < e) {
        int pos = atomicAdd(&g_wp[g_edst[i]], 1);
        g_csrsrc[pos] = g_esrc[i];
    }
}

// ---------------- weight packing ----------------
__global__ void k_packw(
    const float* q1w, const float* k1w, const float* v1w, const float* s1w,
    const float* q1b, const float* k1b, const float* v1b, const float* s1b,
    const float* q2w, const float* k2w, const float* v2w, const float* s2w,
    const float* q2b, const float* k2b, const float* v2b, const float* s2b)
{
    const float SC1 = 0.17677669529663687f;   // 1/sqrt(32)
    const float SC2 = 0.15811388300841897f;   // 1/sqrt(40)
    int i = blockIdx.x * blockDim.x + threadIdx.x;
    const int W1 = NTOT1 * FIN, W2 = N2P * D1;
    if (i < W1) {
        int n = i / FIN, k = i % FIN;
        const float* s = (n < 256) ? q1w : (n < 512) ? k1w : (n < 768) ? v1w : s1w;
        float v = s[k * 256 + (n & 255)];
        if (n < 256) v *= SC1;
        __nv_bfloat16 h = __float2bfloat16(v);
        g_w1hi[i] = h;
        g_w1lo[i] = __float2bfloat16(v - __bfloat162float(h));
    } else if (i < W1 + W2) {
        int j = i - W1;
        int n = j / D1, k = j % D1;
        float v = 0.f;
        if (n < NTOT2) {
            const float* s = (n < 40) ? q2w : (n < 80) ? k2w : (n < 120) ? v2w : s2w;
            v = s[k * 40 + (n % 40)];
            if (n < 40) v *= SC2;
        }
        __nv_bfloat16 h = __float2bfloat16(v);
        g_w2hi[j] = h;
        g_w2lo[j] = __float2bfloat16(v - __bfloat162float(h));
    } else if (i < W1 + W2 + NTOT1) {
        int c = i - W1 - W2;
        const float* s = (c < 256) ? q1b : (c < 512) ? k1b : (c < 768) ? v1b : s1b;
        float v = s[c & 255];
        if (c < 256) v *= SC1;
        g_b1[c] = v;
    } else if (i < W1 + W2 + NTOT1 + N2P) {
        int c = i - W1 - W2 - NTOT1;
        float v = 0.f;
        if (c < NTOT2) {
            const float* s = (c < 40) ? q2b : (c < 80) ? k2b : (c < 120) ? v2b : s2b;
            v = s[c % 40];
            if (c < 40) v *= SC2;
        }
        g_b2[c] = v;
    }
}

// ---------------- split fp32 -> bf16 hi/lo (vectorized) ----------------
__global__ void k_split(const float* __restrict__ src,
                        __nv_bfloat16* __restrict__ hi,
                        __nv_bfloat16* __restrict__ lo, int total4)
{
    int i = blockIdx.x * blockDim.x + threadIdx.x;
    if (i >= total4) return;
    float4 v = *(const float4*)&src[i * 4];
    float vv[4] = { v.x, v.y, v.z, v.w };
    __nv_bfloat162 ph[2], pl[2];
    #pragma unroll
    for (int j = 0; j < 2; j++) {
        __nv_bfloat16 h0 = __float2bfloat16(vv[2*j]);
        __nv_bfloat16 h1 = __float2bfloat16(vv[2*j+1]);
        ph[j] = __halves2bfloat162(h0, h1);
        pl[j] = __halves2bfloat162(__float2bfloat16(vv[2*j]   - __bfloat162float(h0)),
                                   __float2bfloat16(vv[2*j+1] - __bfloat162float(h1)));
    }
    *(uint2*)&hi[i * 4] = *(uint2*)ph;
    *(uint2*)&lo[i * 4] = *(uint2*)pl;
}

// ---------------- mma.sync bf16 split GEMM ----------------
__device__ __forceinline__ void mma16816(float* c, const uint32_t* a, const uint32_t* b) {
    asm volatile(
        "mma.sync.aligned.m16n8k16.row.col.f32.bf16.bf16.f32 "
        "{%0,%1,%2,%3}, {%4,%5,%6,%7}, {%8,%9}, {%0,%1,%2,%3};\n"
        : "+f"(c[0]), "+f"(c[1]), "+f"(c[2]), "+f"(c[3])
        : "r"(a[0]), "r"(a[1]), "r"(a[2]), "r"(a[3]), "r"(b[0]), "r"(b[1]));
}
#define LDSM4(r, addr) \
    asm volatile("ldmatrix.sync.aligned.m8n8.x4.shared.b16 {%0,%1,%2,%3}, [%4];" \
        : "=r"((r)[0]), "=r"((r)[1]), "=r"((r)[2]), "=r"((r)[3]) : "r"(addr))
#define CPASYNC16(saddr, gptr) \
    asm volatile("cp.async.cg.shared.global [%0], [%1], 16;" :: "r"(saddr), "l"(gptr))
#define CPASYNC_FENCE() \
    asm volatile("cp.async.commit_group;\n\tcp.async.wait_group 0;" ::: "memory")

__device__ __forceinline__ uint32_t smem_u32(const void* p) {
    uint32_t a;
    asm("{ .reg .u64 t; cvta.to.shared.u64 t, %1; cvt.u32.u64 %0, t; }" : "=r"(a) : "l"(p));
    return a;
}

#define SMSTR 72     // bf16 row stride (64 data + 8 pad); 144B row, 16B aligned
#define TILEB (128 * SMSTR)

// C[M,*] = A[M,K] @ B^T[N,K] + bias ; 3-term split-bf16 in ONE k-pass.
// All staging via cp.async (A and B pre-split bf16). Single-buffered (73.7KB,
// preserves ~80KB L1D for the L2/L1-cached A/B global reads).
template <int KCHUNKS>
__global__ void __launch_bounds__(256, 2) k_mma2(
    const __nv_bfloat16* __restrict__ Ahi, const __nv_bfloat16* __restrict__ Alo,
    const __nv_bfloat16* __restrict__ Bhi, const __nv_bfloat16* __restrict__ Blo,
    const float* __restrict__ bias, float* __restrict__ C,
    int M, int Nvalid, int ldc)
{
    constexpr int K = KCHUNKS * 64;
    extern __shared__ __nv_bfloat16 smem[];
    __nv_bfloat16* AsH = smem;
    __nv_bfloat16* AsL = smem + TILEB;

    const int tid = threadIdx.x, lane = tid & 31, wid = tid >> 5;
    const int wm = wid & 1, wn = wid >> 1;      // warps 2(M) x 4(N); warp tile 64x32
    const int grp = lane >> 2, thr = lane & 3;
    const int sub = lane >> 3, lr = lane & 7;
    const int m0 = blockIdx.y * 128, n0 = blockIdx.x * 128;

    const uint32_t sAH = smem_u32(smem);
    const uint32_t sAL = sAH + TILEB * 2;
    const uint32_t sBH = sAH + 2 * TILEB * 2;
    const uint32_t sBL = sAH + 3 * TILEB * 2;
    const int rA = wm * 64 + lr + (sub & 1) * 8;
    const int kA = (sub >> 1) * 8;
    const int rB = wn * 32 + (sub >> 1) * 8 + lr;
    const int kB = (sub & 1) * 8;
    const bool active = (n0 + wn * 32) < Nvalid;   // skip MMA for all-padding warps

    float c[4][4][4];
    #pragma unroll
    for (int mt = 0; mt < 4; mt++)
        #pragma unroll
        for (int nt = 0; nt < 4; nt++)
            #pragma unroll
            for (int r = 0; r < 4; r++) c[mt][nt][r] = 0.f;

    for (int kc = 0; kc < KCHUNKS; kc++) {
        const int kk = kc * 64;
        // ---- async-stage all 4 tiles ----
        #pragma unroll
        for (int i = 0; i < 4; i++) {
            int q = tid + i * 256;
            int r = q >> 3, s = q & 7;
            uint32_t soff = (uint32_t)(r * SMSTR + s * 8) * 2;
            CPASYNC16(sBH + soff, &Bhi[(size_t)(n0 + r) * K + kk + s * 8]);
            CPASYNC16(sBL + soff, &Blo[(size_t)(n0 + r) * K + kk + s * 8]);
            int grow = m0 + r;
            if (grow < M) {
                CPASYNC16(sAH + soff, &Ahi[(size_t)grow * K + kk + s * 8]);
                CPASYNC16(sAL + soff, &Alo[(size_t)grow * K + kk + s * 8]);
            } else {
                *(uint4*)&AsH[r * SMSTR + s * 8] = make_uint4(0u, 0u, 0u, 0u);
                *(uint4*)&AsL[r * SMSTR + s * 8] = make_uint4(0u, 0u, 0u, 0u);
            }
        }
        CPASYNC_FENCE();
        __syncthreads();

        if (active) {
            #pragma unroll
            for (int ks = 0; ks < 4; ks++) {
                const int kb = ks * 16;
                uint32_t ah[4][4], bh[2][4], t[2][4], al4[4];
                #pragma unroll
                for (int mt = 0; mt < 4; mt++)
                    LDSM4(ah[mt], sAH + ((rA + mt * 16) * SMSTR + kb + kA) * 2);
                #pragma unroll
                for (int p = 0; p < 2; p++)
                    LDSM4(bh[p], sBH + ((rB + p * 16) * SMSTR + kb + kB) * 2);
                #pragma unroll
                for (int mt = 0; mt < 4; mt++)
                    #pragma unroll
                    for (int p = 0; p < 2; p++) {
                        mma16816(c[mt][2 * p],     ah[mt], &bh[p][0]);
                        mma16816(c[mt][2 * p + 1], ah[mt], &bh[p][2]);
                    }
                #pragma unroll
                for (int p = 0; p < 2; p++)
                    LDSM4(t[p], sBL + ((rB + p * 16) * SMSTR + kb + kB) * 2);
                #pragma unroll
                for (int mt = 0; mt < 4; mt++)
                    #pragma unroll
                    for (int p = 0; p < 2; p++) {
                        mma16816(c[mt][2 * p],     ah[mt], &t[p][0]);
                        mma16816(c[mt][2 * p + 1], ah[mt], &t[p][2]);
                    }
                #pragma unroll
                for (int mt = 0; mt < 4; mt++) {
                    LDSM4(al4, sAL + ((rA + mt * 16) * SMSTR + kb + kA) * 2);
                    #pragma unroll
                    for (int p = 0; p < 2; p++) {
                        mma16816(c[mt][2 * p],     al4, &bh[p][0]);
                        mma16816(c[mt][2 * p + 1], al4, &bh[p][2]);
                    }
                }
            }
        }
        __syncthreads();
    }

    #pragma unroll
    for (int mt = 0; mt < 4; mt++) {
        int row = m0 + wm * 64 + mt * 16 + grp;
        #pragma unroll
        for (int nt = 0; nt < 4; nt++) {
            int col = n0 + wn * 32 + nt * 8 + thr * 2;
            if (col >= Nvalid) continue;
            float b0 = bias[col], b1 = bias[col + 1];
            if (row < M)
                *(float2*)&C[(size_t)row * ldc + col] =
                    make_float2(c[mt][nt][0] + b0, c[mt][nt][1] + b1);
            if (row + 8 < M)
                *(float2*)&C[(size_t)(row + 8) * ldc + col] =
                    make_float2(c[mt][nt][2] + b0, c[mt][nt][3] + b1);
        }
    }
}

// ---------------- fused layer-1 edge pass (unrolled x2 gather) ----------------
__global__ void __launch_bounds__(256) k_edge1(const float* __restrict__ bw, int n)
{
    __shared__ float w[3 * D1];
    for (int i = threadIdx.x; i < 3 * D1; i += blockDim.x) w[i] = bw[i];
    __syncthreads();

    int warp = (blockIdx.x * blockDim.x + threadIdx.x) >> 5;
    int lane = threadIdx.x & 31;
    if (warp >= n) return;
    int s0 = g_rowptr[warp], s1 = g_rowptr[warp + 1];

    const float* prow = g_p1 + (size_t)warp * NTOT1;
    float4 qa = *(const float4*)(prow + lane * 8);
    float4 qb = *(const float4*)(prow + lane * 8 + 4);

    float a0x=0,a0y=0,a0z=0,a0w=0, a1x=0,a1y=0,a1z=0,a1w=0;
    float asum = 0.f;
    int s = s0;
    for (; s + 1 < s1; s += 2) {
        int src0 = g_csrsrc[s], src1 = g_csrsrc[s + 1];
        const float* b0p = g_p1 + (size_t)src0 * NTOT1;
        const float* b1p = g_p1 + (size_t)src1 * NTOT1;
        float4 ka0 = *(const float4*)(b0p + 256 + lane * 8);
        float4 kb0 = *(const float4*)(b0p + 256 + lane * 8 + 4);
        float4 ka1 = *(const float4*)(b1p + 256 + lane * 8);
        float4 kb1 = *(const float4*)(b1p + 256 + lane * 8 + 4);
        float4 v00 = *(const float4*)(b0p + 512 + lane * 8);
        float4 v01 = *(const float4*)(b0p + 512 + lane * 8 + 4);
        float4 v10 = *(const float4*)(b1p + 512 + lane * 8);
        float4 v11 = *(const float4*)(b1p + 512 + lane * 8 + 4);

        float p0 = qa.x*ka0.x + qa.y*ka0.y + qa.z*ka0.z + qa.w*ka0.w
                 + qb.x*kb0.x + qb.y*kb0.y + qb.z*kb0.z + qb.w*kb0.w;
        float p1 = qa.x*ka1.x + qa.y*ka1.y + qa.z*ka1.z + qa.w*ka1.w
                 + qb.x*kb1.x + qb.y*kb1.y + qb.z*kb1.z + qb.w*kb1.w;
        p0 += __shfl_xor_sync(0xffffffffu, p0, 1);
        p0 += __shfl_xor_sync(0xffffffffu, p0, 2);
        p1 += __shfl_xor_sync(0xffffffffu, p1, 1);
        p1 += __shfl_xor_sync(0xffffffffu, p1, 2);
        float e0 = expf(p0), e1 = expf(p1);   // q pre-scaled by 1/sqrt(32)
        asum += e0 + e1;
        a0x = fmaf(e0, v00.x, a0x); a0y = fmaf(e0, v00.y, a0y);
        a0z = fmaf(e0, v00.z, a0z); a0w = fmaf(e0, v00.w, a0w);
        a1x = fmaf(e0, v01.x, a1x); a1y = fmaf(e0, v01.y, a1y);
        a1z = fmaf(e0, v01.z, a1z); a1w = fmaf(e0, v01.w, a1w);
        a0x = fmaf(e1, v10.x, a0x); a0y = fmaf(e1, v10.y, a0y);
        a0z = fmaf(e1, v10.z, a0z); a0w = fmaf(e1, v10.w, a0w);
        a1x = fmaf(e1, v11.x, a1x); a1y = fmaf(e1, v11.y, a1y);
        a1z = fmaf(e1, v11.z, a1z); a1w = fmaf(e1, v11.w, a1w);
    }
    if (s < s1) {
        int src = g_csrsrc[s];
        const float* base = g_p1 + (size_t)src * NTOT1;
        float4 ka = *(const float4*)(base + 256 + lane * 8);
        float4 kb = *(const float4*)(base + 256 + lane * 8 + 4);
        float4 v0 = *(const float4*)(base + 512 + lane * 8);
        float4 v1 = *(const float4*)(base + 512 + lane * 8 + 4);
        float p = qa.x*ka.x + qa.y*ka.y + qa.z*ka.z + qa.w*ka.w
                + qb.x*kb.x + qb.y*kb.y + qb.z*kb.z + qb.w*kb.w;
        p += __shfl_xor_sync(0xffffffffu, p, 1);
        p += __shfl_xor_sync(0xffffffffu, p, 2);
        float e = expf(p);
        asum += e;
        a0x = fmaf(e, v0.x, a0x); a0y = fmaf(e, v0.y, a0y);
        a0z = fmaf(e, v0.z, a0z); a0w = fmaf(e, v0.w, a0w);
        a1x = fmaf(e, v1.x, a1x); a1y = fmaf(e, v1.y, a1y);
        a1z = fmaf(e, v1.z, a1z); a1w = fmaf(e, v1.w, a1w);
    }
    float inv = (s1 > s0) ? 1.0f / asum : 0.f;
    float o[8] = { a0x*inv, a0y*inv, a0z*inv, a0w*inv, a1x*inv, a1y*inv, a1z*inv, a1w*inv };

    float4 sa = *(const float4*)(prow + 768 + lane * 8);
    float4 sbv = *(const float4*)(prow + 768 + lane * 8 + 4);
    float sk[8] = { sa.x, sa.y, sa.z, sa.w, sbv.x, sbv.y, sbv.z, sbv.w };

    float g = 0.f;
    #pragma unroll
    for (int j = 0; j < 8; j++) {
        int ccol = lane * 8 + j;
        g += o[j] * w[ccol] + sk[j] * w[D1 + ccol] + (o[j] - sk[j]) * w[2 * D1 + ccol];
    }
    #pragma unroll
    for (int off = 16; off >= 1; off >>= 1) g += __shfl_xor_sync(0xffffffffu, g, off);
    float beta = 1.0f / (1.0f + expf(-g));

    __nv_bfloat162 ph[4], pl[4];
    #pragma unroll
    for (int j = 0; j < 4; j++) {
        float v0 = beta * sk[2*j]   + (1.0f - beta) * o[2*j];
        float v1 = beta * sk[2*j+1] + (1.0f - beta) * o[2*j+1];
        v0 = (v0 > 0.f) ? v0 : (expf(v0) - 1.0f);   // ELU
        v1 = (v1 > 0.f) ? v1 : (expf(v1) - 1.0f);
        __nv_bfloat16 h0 = __float2bfloat16(v0), h1 = __float2bfloat16(v1);
        ph[j] = __halves2bfloat162(h0, h1);
        pl[j] = __halves2bfloat162(__float2bfloat16(v0 - __bfloat162float(h0)),
                                   __float2bfloat16(v1 - __bfloat162float(h1)));
    }
    *(uint4*)&g_hhi[(size_t)warp * D1 + lane * 8] = *(uint4*)ph;
    *(uint4*)&g_hlo[(size_t)warp * D1 + lane * 8] = *(uint4*)pl;
}

// ---------------- fused layer-2 edge pass (unrolled x2 gather) ----------------
__global__ void __launch_bounds__(256) k_edge2(const float* __restrict__ bw,
                                               float* __restrict__ out, int n)
{
    __shared__ float w[3 * NOUT];
    for (int i = threadIdx.x; i < 3 * NOUT; i += blockDim.x) w[i] = bw[i];
    __syncthreads();

    int warp = (blockIdx.x * blockDim.x + threadIdx.x) >> 5;
    int lane = threadIdx.x & 31;
    if (warp >= n) return;
    int s0 = g_rowptr[warp], s1 = g_rowptr[warp + 1];

    const float* prow = g_p2 + (size_t)warp * NTOT2;
    float q0 = 0.f, q1 = 0.f;
    if (lane < 20) {
        float2 qq = *(const float2*)(prow + lane * 2);
        q0 = qq.x; q1 = qq.y;
    }
    float acc0 = 0.f, acc1 = 0.f, asum = 0.f;
    int s = s0;
    for (; s + 1 < s1; s += 2) {
        int src0 = g_csrsrc[s], src1 = g_csrsrc[s + 1];
        const float* b0p = g_p2 + (size_t)src0 * NTOT2;
        const float* b1p = g_p2 + (size_t)src1 * NTOT2;
        float p0 = 0.f, p1 = 0.f;
        float v00 = 0.f, v01 = 0.f, v10 = 0.f, v11 = 0.f;
        if (lane < 20) {
            float2 k0 = *(const float2*)(b0p + 40 + lane * 2);
            float2 k1 = *(const float2*)(b1p + 40 + lane * 2);
            float2 w0 = *(const float2*)(b0p + 80 + lane * 2);
            float2 w1 = *(const float2*)(b1p + 80 + lane * 2);
            p0 = q0 * k0.x + q1 * k0.y;
            p1 = q0 * k1.x + q1 * k1.y;
            v00 = w0.x; v01 = w0.y; v10 = w1.x; v11 = w1.y;
        }
        #pragma unroll
        for (int off = 16; off >= 1; off >>= 1) {
            p0 += __shfl_xor_sync(0xffffffffu, p0, off);
            p1 += __shfl_xor_sync(0xffffffffu, p1, off);
        }
        float e0 = expf(p0), e1 = expf(p1);   // q pre-scaled by 1/sqrt(40)
        asum += e0 + e1;
        acc0 = fmaf(e0, v00, acc0); acc1 = fmaf(e0, v01, acc1);
        acc0 = fmaf(e1, v10, acc0); acc1 = fmaf(e1, v11, acc1);
    }
    if (s < s1) {
        int src = g_csrsrc[s];
        const float* base = g_p2 + (size_t)src * NTOT2;
        float p = 0.f, v0 = 0.f, v1 = 0.f;
        if (lane < 20) {
            float2 kk = *(const float2*)(base + 40 + lane * 2);
            p = q0 * kk.x + q1 * kk.y;
            float2 vv = *(const float2*)(base + 80 + lane * 2);
            v0 = vv.x; v1 = vv.y;
        }
        #pragma unroll
        for (int off = 16; off >= 1; off >>= 1) p += __shfl_xor_sync(0xffffffffu, p, off);
        float e = expf(p);
        asum += e;
        acc0 = fmaf(e, v0, acc0);
        acc1 = fmaf(e, v1, acc1);
    }
    float inv = (s1 > s0) ? 1.0f / asum : 0.f;
    float o0 = acc0 * inv, o1 = acc1 * inv;

    float sk0 = 0.f, sk1 = 0.f, g = 0.f;
    if (lane < 20) {
        float2 ss = *(const float2*)(prow + 120 + lane * 2);
        sk0 = ss.x; sk1 = ss.y;
        int ccol = lane * 2;
        g = o0 * w[ccol]     + sk0 * w[NOUT + ccol]     + (o0 - sk0) * w[2 * NOUT + ccol]
          + o1 * w[ccol + 1] + sk1 * w[NOUT + ccol + 1] + (o1 - sk1) * w[2 * NOUT + ccol + 1];
    }
    #pragma unroll
    for (int off = 16; off >= 1; off >>= 1) g += __shfl_xor_sync(0xffffffffu, g, off);
    float beta = 1.0f / (1.0f + expf(-g));
    if (lane < 20) {
        float r0 = beta * sk0 + (1.0f - beta) * o0;
        float r1 = beta * sk1 + (1.0f - beta) * o1;
        *(float2*)(out + (size_t)warp * NOUT + lane * 2) = make_float2(r0, r1);
    }
}

// ---------------- launch ----------------
extern "C" void kernel_launch(void* const* d_in, const int* in_sizes, int n_in,
                              void* d_out, int out_size)
{
    const float* x = (const float*)d_in[0];
    const void* ei = d_in[1];
    const float* q1w = (const float*)d_in[2];
    const float* q1b = (const float*)d_in[3];
    const float* k1w = (const float*)d_in[4];
    const float* k1b = (const float*)d_in[5];
    const float* v1w = (const float*)d_in[6];
    const float* v1b = (const float*)d_in[7];
    const float* s1w = (const float*)d_in[8];
    const float* s1b = (const float*)d_in[9];
    const float* b1w = (const float*)d_in[10];
    const float* q2w = (const float*)d_in[11];
    const float* q2b = (const float*)d_in[12];
    const float* k2w = (const float*)d_in[13];
    const float* k2b = (const float*)d_in[14];
    const float* v2w = (const float*)d_in[15];
    const float* v2b = (const float*)d_in[16];
    const float* s2w = (const float*)d_in[17];
    const float* s2b = (const float*)d_in[18];
    const float* b2w = (const float*)d_in[19];
    float* out = (float*)d_out;

    const int n = in_sizes[0] / FIN;   // 50000
    const int e = in_sizes[1] / 2;     // 800000

    float* d_p1; cudaGetSymbolAddress((void**)&d_p1, g_p1);
    float* d_p2; cudaGetSymbolAddress((void**)&d_p2, g_p2);
    __nv_bfloat16 *d_xhi, *d_xlo, *d_hhi, *d_hlo, *d_w1hi, *d_w1lo, *d_w2hi, *d_w2lo;
    cudaGetSymbolAddress((void**)&d_xhi, g_xhi);
    cudaGetSymbolAddress((void**)&d_xlo, g_xlo);
    cudaGetSymbolAddress((void**)&d_hhi, g_hhi);
    cudaGetSymbolAddress((void**)&d_hlo, g_hlo);
    cudaGetSymbolAddress((void**)&d_w1hi, g_w1hi);
    cudaGetSymbolAddress((void**)&d_w1lo, g_w1lo);
    cudaGetSymbolAddress((void**)&d_w2hi, g_w2hi);
    cudaGetSymbolAddress((void**)&d_w2lo, g_w2lo);
    float *d_b1, *d_b2;
    cudaGetSymbolAddress((void**)&d_b1, g_b1);
    cudaGetSymbolAddress((void**)&d_b2, g_b2);

    static cudaStream_t s2 = 0;
    static cudaEvent_t evA = 0, evB = 0;
    if (!s2)  cudaStreamCreateWithFlags(&s2, cudaStreamNonBlocking);
    if (!evA) cudaEventCreateWithFlags(&evA, cudaEventDisableTiming);
    if (!evB) cudaEventCreateWithFlags(&evB, cudaEventDisableTiming);

    const int GSMEM = 4 * TILEB * 2;  // 73728 B (2 CTA/SM; L1D keeps ~80KB)
    cudaFuncSetAttribute((const void*)k_mma2<2>, cudaFuncAttributeMaxDynamicSharedMemorySize, GSMEM);
    cudaFuncSetAttribute((const void*)k_mma2<4>, cudaFuncAttributeMaxDynamicSharedMemorySize, GSMEM);

    const int mblocks = cdiv(n, 128);
    const int nodeBlocks = cdiv(n * 32, 256);

    // fork immediately: CSR chain (no deps on main-stream work)
    cudaEventRecord(evA, 0);
    cudaStreamWaitEvent(s2, evA, 0);

    k_init<<<cdiv(n, 256), 256, 0, s2>>>(n);                       // s2
    k_detect<<<cdiv(e, 256), 256, 0, s2>>>((const int*)ei, e);     // s2
    const int packTotal = NTOT1 * FIN + N2P * D1 + NTOT1 + N2P;
    k_packw<<<cdiv(packTotal, 256), 256>>>(                        // main
        q1w, k1w, v1w, s1w, q1b, k1b, v1b, s1b,
        q2w, k2w, v2w, s2w, q2b, k2b, v2b, s2b);
    k_split<<<cdiv(n * FIN / 4, 256), 256>>>(x, d_xhi, d_xlo, n * FIN / 4);  // main
    k_mma2<2><<<dim3(NTOT1 / 128, mblocks), 256, GSMEM>>>(         // main
        d_xhi, d_xlo, d_w1hi, d_w1lo, d_b1, d_p1, n, NTOT1, NTOT1);

    k_convhist<<<cdiv(e, 256), 256, 0, s2>>>(ei, e);               // s2
    k_scan<<<1, 1024, 0, s2>>>(n);                                 // s2
    k_scatter<<<cdiv(e, 256), 256, 0, s2>>>(e);                    // s2
    cudaEventRecord(evB, s2);

    // join: edge1 needs gemm1 (main) + CSR (s2)
    cudaStreamWaitEvent(0, evB, 0);
    k_edge1<<<nodeBlocks, 256>>>(b1w, n);

    // ---- layer 2 ----
    k_mma2<4><<<dim3(N2P / 128, mblocks), 256, GSMEM>>>(
        d_hhi, d_hlo, d_w2hi, d_w2lo, d_b2, d_p2, n, NTOT2, NTOT2);
    k_edge2<<<nodeBlocks, 256>>>(b2w, out, n);
}

// round 15
// speedup vs baseline: 1.7701x; 1.1157x over previous
#include <cuda_runtime.h>
#include <cuda_bf16.h>
#include <cuda_fp16.h>
#include <math.h>
#include <stdint.h>

// Problem constants
#define NN   50000
#define EE   800000
#define FIN  128
#define D1   256
#define NOUT 40
#define NTOT1 1024   // packed q|k|v|s layer 1 (4*256)
#define NTOT2 160    // packed q|k|v|s layer 2 (4*40)
#define N2P  256     // padded layer-2 N for GEMM tiles

// ---------------- static scratch ----------------
__device__ __align__(256) float g_p1[(size_t)NN * NTOT1];  // q1 (0-255) | s1 (768-1023) fp32
__device__ __align__(256) __half g_kv1[(size_t)NN * 512];  // k1 (0-255) | v1 (256-511) fp16
__device__ __align__(256) float g_p2[(size_t)NN * NTOT2];  // packed q2|k2|v2|s2

__device__ __align__(256) __nv_bfloat16 g_xhi[(size_t)NN * FIN];
__device__ __align__(256) __nv_bfloat16 g_xlo[(size_t)NN * FIN];
__device__ __align__(256) __nv_bfloat16 g_hhi[(size_t)NN * D1];
__device__ __align__(256) __nv_bfloat16 g_hlo[(size_t)NN * D1];
__device__ __align__(256) __nv_bfloat16 g_w1hi[NTOT1 * FIN];  // [n][k] transposed
__device__ __align__(256) __nv_bfloat16 g_w1lo[NTOT1 * FIN];
__device__ __align__(256) __nv_bfloat16 g_w2hi[N2P * D1];     // [n][k], rows >=160 zero
__device__ __align__(256) __nv_bfloat16 g_w2lo[N2P * D1];
__device__ __align__(256) float g_b1[NTOT1];
__device__ __align__(256) float g_b2[N2P];

__device__ __align__(256) int g_esrc[EE];
__device__ __align__(256) int g_edst[EE];
__device__ int g_is32;
__device__ int g_deg[NN];
__device__ __align__(256) int g_rowptr[NN + 1];
__device__ int g_wp[NN];
__device__ __align__(256) int g_csrsrc[EE];

static inline int cdiv(int a, int b) { return (a + b - 1) / b; }

// ---------------- init + edge dtype detect ----------------
__global__ void k_init(int n) {
    int i = blockIdx.x * blockDim.x + threadIdx.x;
    if (i == 0) g_is32 = 0;
    if (i < n) g_deg[i] = 0;
}
__global__ void k_detect(const int* __restrict__ w, int e) {
    int i = blockIdx.x * blockDim.x + threadIdx.x;
    if (i < e) { if (w[2 * i + 1] != 0) g_is32 = 1; }
}
// fused convert + degree histogram
__global__ void k_convhist(const void* __restrict__ ei, int e) {
    int i = blockIdx.x * blockDim.x + threadIdx.x;
    if (i >= e) return;
    int s_, d_;
    if (g_is32) {
        const int* p = (const int*)ei;
        s_ = p[i]; d_ = p[e + i];
    } else {
        const long long* p = (const long long*)ei;
        s_ = (int)p[i]; d_ = (int)p[e + i];
    }
    g_esrc[i] = s_;
    g_edst[i] = d_;
    atomicAdd(&g_deg[d_], 1);
}

// ---------------- CSR: warp-shfl scan + scatter ----------------
__global__ void k_scan(int n) {   // single block, 1024 threads
    __shared__ int wsum[32];
    const int tid = threadIdx.x, lane = tid & 31, wid = tid >> 5;
    int carry = 0;
    for (int base = 0; base <= n; base += 1024) {
        int idx = base + tid;
        int v = (idx < n) ? g_deg[idx] : 0;
        int x = v;
        #pragma unroll
        for (int o = 1; o < 32; o <<= 1) {
            int t = __shfl_up_sync(0xffffffffu, x, o);
            if (lane >= o) x += t;
        }
        if (lane == 31) wsum[wid] = x;
        __syncthreads();
        if (wid == 0) {
            int w = wsum[lane];
            #pragma unroll
            for (int o = 1; o < 32; o <<= 1) {
                int t = __shfl_up_sync(0xffffffffu, w, o);
                if (lane >= o) w += t;
            }
            wsum[lane] = w;
        }
        __syncthreads();
        int pre = wid ? wsum[wid - 1] : 0;
        int excl = carry + pre + x - v;
        if (idx <= n) {
            g_rowptr[idx] = excl;
            if (idx < n) g_wp[idx] = excl;
        }
        carry += wsum[31];
        __syncthreads();
    }
}
__global__ void k_scatter(int e) {
    int i = blockIdx.x * blockDim.x + threadIdx.x;
    if (i < e) {
        int pos = atomicAdd(&g_wp[g_edst[i]], 1);
        g_csrsrc[pos] = g_esrc[i];
    }
}

// ---------------- weight packing ----------------
__global__ void k_packw(
    const float* q1w, const float* k1w, const float* v1w, const float* s1w,
    const float* q1b, const float* k1b, const float* v1b, const float* s1b,
    const float* q2w, const float* k2w, const float* v2w, const float* s2w,
    const float* q2b, const float* k2b, const float* v2b, const float* s2b)
{
    const float SC1 = 0.17677669529663687f;   // 1/sqrt(32)
    const float SC2 = 0.15811388300841897f;   // 1/sqrt(40)
    int i = blockIdx.x * blockDim.x + threadIdx.x;
    const int W1 = NTOT1 * FIN, W2 = N2P * D1;
    if (i < W1) {
        int n = i / FIN, k = i % FIN;
        const float* s = (n < 256) ? q1w : (n < 512) ? k1w : (n < 768) ? v1w : s1w;
        float v = s[k * 256 + (n & 255)];
        if (n < 256) v *= SC1;
        __nv_bfloat16 h = __float2bfloat16(v);
        g_w1hi[i] = h;
        g_w1lo[i] = __float2bfloat16(v - __bfloat162float(h));
    } else if (i < W1 + W2) {
        int j = i - W1;
        int n = j / D1, k = j % D1;
        float v = 0.f;
        if (n < NTOT2) {
            const float* s = (n < 40) ? q2w : (n < 80) ? k2w : (n < 120) ? v2w : s2w;
            v = s[k * 40 + (n % 40)];
            if (n < 40) v *= SC2;
        }
        __nv_bfloat16 h = __float2bfloat16(v);
        g_w2hi[j] = h;
        g_w2lo[j] = __float2bfloat16(v - __bfloat162float(h));
    } else if (i < W1 + W2 + NTOT1) {
        int c = i - W1 - W2;
        const float* s = (c < 256) ? q1b : (c < 512) ? k1b : (c < 768) ? v1b : s1b;
        float v = s[c & 255];
        if (c < 256) v *= SC1;
        g_b1[c] = v;
    } else if (i < W1 + W2 + NTOT1 + N2P) {
        int c = i - W1 - W2 - NTOT1;
        float v = 0.f;
        if (c < NTOT2) {
            const float* s = (c < 40) ? q2b : (c < 80) ? k2b : (c < 120) ? v2b : s2b;
            v = s[c % 40];
            if (c < 40) v *= SC2;
        }
        g_b2[c] = v;
    }
}

// ---------------- split fp32 -> bf16 hi/lo (vectorized) ----------------
__global__ void k_split(const float* __restrict__ src,
                        __nv_bfloat16* __restrict__ hi,
                        __nv_bfloat16* __restrict__ lo, int total4)
{
    int i = blockIdx.x * blockDim.x + threadIdx.x;
    if (i >= total4) return;
    float4 v = *(const float4*)&src[i * 4];
    float vv[4] = { v.x, v.y, v.z, v.w };
    __nv_bfloat162 ph[2], pl[2];
    #pragma unroll
    for (int j = 0; j < 2; j++) {
        __nv_bfloat16 h0 = __float2bfloat16(vv[2*j]);
        __nv_bfloat16 h1 = __float2bfloat16(vv[2*j+1]);
        ph[j] = __halves2bfloat162(h0, h1);
        pl[j] = __halves2bfloat162(__float2bfloat16(vv[2*j]   - __bfloat162float(h0)),
                                   __float2bfloat16(vv[2*j+1] - __bfloat162float(h1)));
    }
    *(uint2*)&hi[i * 4] = *(uint2*)ph;
    *(uint2*)&lo[i * 4] = *(uint2*)pl;
}

// ---------------- mma.sync bf16 split GEMM ----------------
__device__ __forceinline__ void mma16816(float* c, const uint32_t* a, const uint32_t* b) {
    asm volatile(
        "mma.sync.aligned.m16n8k16.row.col.f32.bf16.bf16.f32 "
        "{%0,%1,%2,%3}, {%4,%5,%6,%7}, {%8,%9}, {%0,%1,%2,%3};\n"
        : "+f"(c[0]), "+f"(c[1]), "+f"(c[2]), "+f"(c[3])
        : "r"(a[0]), "r"(a[1]), "r"(a[2]), "r"(a[3]), "r"(b[0]), "r"(b[1]));
}
#define LDSM4(r, addr) \
    asm volatile("ldmatrix.sync.aligned.m8n8.x4.shared.b16 {%0,%1,%2,%3}, [%4];" \
        : "=r"((r)[0]), "=r"((r)[1]), "=r"((r)[2]), "=r"((r)[3]) : "r"(addr))
#define CPASYNC16(saddr, gptr) \
    asm volatile("cp.async.cg.shared.global [%0], [%1], 16;" :: "r"(saddr), "l"(gptr))
#define CPASYNC_FENCE() \
    asm volatile("cp.async.commit_group;\n\tcp.async.wait_group 0;" ::: "memory")

__device__ __forceinline__ uint32_t smem_u32(const void* p) {
    uint32_t a;
    asm("{ .reg .u64 t; cvta.to.shared.u64 t, %1; cvt.u32.u64 %0, t; }" : "=r"(a) : "l"(p));
    return a;
}

#define SMSTR 72     // bf16 row stride (64 data + 8 pad); 144B row, 16B aligned
#define TILEB (128 * SMSTR)

// C[M,*] = A[M,K] @ B^T[N,K] + bias ; 3-term split-bf16 in ONE k-pass.
// MODE 0: plain fp32 C.  MODE 1 (gemm1): cols [256,768) -> fp16 g_kv1, rest fp32 C.
template <int KCHUNKS, int MODE>
__global__ void __launch_bounds__(256, 2) k_mma2(
    const __nv_bfloat16* __restrict__ Ahi, const __nv_bfloat16* __restrict__ Alo,
    const __nv_bfloat16* __restrict__ Bhi, const __nv_bfloat16* __restrict__ Blo,
    const float* __restrict__ bias, float* __restrict__ C,
    int M, int Nvalid, int ldc)
{
    constexpr int K = KCHUNKS * 64;
    extern __shared__ __nv_bfloat16 smem[];
    __nv_bfloat16* AsH = smem;
    __nv_bfloat16* AsL = smem + TILEB;

    const int tid = threadIdx.x, lane = tid & 31, wid = tid >> 5;
    const int wm = wid & 1, wn = wid >> 1;      // warps 2(M) x 4(N); warp tile 64x32
    const int grp = lane >> 2, thr = lane & 3;
    const int sub = lane >> 3, lr = lane & 7;
    const int m0 = blockIdx.y * 128, n0 = blockIdx.x * 128;

    const uint32_t sAH = smem_u32(smem);
    const uint32_t sAL = sAH + TILEB * 2;
    const uint32_t sBH = sAH + 2 * TILEB * 2;
    const uint32_t sBL = sAH + 3 * TILEB * 2;
    const int rA = wm * 64 + lr + (sub & 1) * 8;
    const int kA = (sub >> 1) * 8;
    const int rB = wn * 32 + (sub >> 1) * 8 + lr;
    const int kB = (sub & 1) * 8;
    const bool active = (n0 + wn * 32) < Nvalid;   // skip MMA for all-padding warps

    float c[4][4][4];
    #pragma unroll
    for (int mt = 0; mt < 4; mt++)
        #pragma unroll
        for (int nt = 0; nt < 4; nt++)
            #pragma unroll
            for (int r = 0; r < 4; r++) c[mt][nt][r] = 0.f;

    for (int kc = 0; kc < KCHUNKS; kc++) {
        const int kk = kc * 64;
        // ---- async-stage all 4 tiles ----
        #pragma unroll
        for (int i = 0; i < 4; i++) {
            int q = tid + i * 256;
            int r = q >> 3, s = q & 7;
            uint32_t soff = (uint32_t)(r * SMSTR + s * 8) * 2;
            CPASYNC16(sBH + soff, &Bhi[(size_t)(n0 + r) * K + kk + s * 8]);
            CPASYNC16(sBL + soff, &Blo[(size_t)(n0 + r) * K + kk + s * 8]);
            int grow = m0 + r;
            if (grow < M) {
                CPASYNC16(sAH + soff, &Ahi[(size_t)grow * K + kk + s * 8]);
                CPASYNC16(sAL + soff, &Alo[(size_t)grow * K + kk + s * 8]);
            } else {
                *(uint4*)&AsH[r * SMSTR + s * 8] = make_uint4(0u, 0u, 0u, 0u);
                *(uint4*)&AsL[r * SMSTR + s * 8] = make_uint4(0u, 0u, 0u, 0u);
            }
        }
        CPASYNC_FENCE();
        __syncthreads();

        if (active) {
            #pragma unroll
            for (int ks = 0; ks < 4; ks++) {
                const int kb = ks * 16;
                uint32_t ah[4][4], bh[2][4], t[2][4], al4[4];
                #pragma unroll
                for (int mt = 0; mt < 4; mt++)
                    LDSM4(ah[mt], sAH + ((rA + mt * 16) * SMSTR + kb + kA) * 2);
                #pragma unroll
                for (int p = 0; p < 2; p++)
                    LDSM4(bh[p], sBH + ((rB + p * 16) * SMSTR + kb + kB) * 2);
                #pragma unroll
                for (int mt = 0; mt < 4; mt++)
                    #pragma unroll
                    for (int p = 0; p < 2; p++) {
                        mma16816(c[mt][2 * p],     ah[mt], &bh[p][0]);
                        mma16816(c[mt][2 * p + 1], ah[mt], &bh[p][2]);
                    }
                #pragma unroll
                for (int p = 0; p < 2; p++)
                    LDSM4(t[p], sBL + ((rB + p * 16) * SMSTR + kb + kB) * 2);
                #pragma unroll
                for (int mt = 0; mt < 4; mt++)
                    #pragma unroll
                    for (int p = 0; p < 2; p++) {
                        mma16816(c[mt][2 * p],     ah[mt], &t[p][0]);
                        mma16816(c[mt][2 * p + 1], ah[mt], &t[p][2]);
                    }
                #pragma unroll
                for (int mt = 0; mt < 4; mt++) {
                    LDSM4(al4, sAL + ((rA + mt * 16) * SMSTR + kb + kA) * 2);
                    #pragma unroll
                    for (int p = 0; p < 2; p++) {
                        mma16816(c[mt][2 * p],     al4, &bh[p][0]);
                        mma16816(c[mt][2 * p + 1], al4, &bh[p][2]);
                    }
                }
            }
        }
        __syncthreads();
    }

    #pragma unroll
    for (int mt = 0; mt < 4; mt++) {
        int row = m0 + wm * 64 + mt * 16 + grp;
        #pragma unroll
        for (int nt = 0; nt < 4; nt++) {
            int col = n0 + wn * 32 + nt * 8 + thr * 2;
            if (col >= Nvalid) continue;
            float b0 = bias[col], b1 = bias[col + 1];
            float r00 = c[mt][nt][0] + b0, r01 = c[mt][nt][1] + b1;
            float r10 = c[mt][nt][2] + b0, r11 = c[mt][nt][3] + b1;
            if (MODE == 1 && col >= 256 && col < 768) {
                // k|v columns -> fp16 kv array (k at 0-255, v at 256-511)
                int kvc = col - 256;
                if (row < M)
                    *(__half2*)&g_kv1[(size_t)row * 512 + kvc] = __floats2half2_rn(r00, r01);
                if (row + 8 < M)
                    *(__half2*)&g_kv1[(size_t)(row + 8) * 512 + kvc] = __floats2half2_rn(r10, r11);
            } else {
                if (row < M)
                    *(float2*)&C[(size_t)row * ldc + col] = make_float2(r00, r01);
                if (row + 8 < M)
                    *(float2*)&C[(size_t)(row + 8) * ldc + col] = make_float2(r10, r11);
            }
        }
    }
}

// ---------------- fused layer-1 edge pass (fp16 k|v gathers, x2 unroll) ----------------
__global__ void __launch_bounds__(256) k_edge1(const float* __restrict__ bw, int n)
{
    __shared__ float w[3 * D1];
    for (int i = threadIdx.x; i < 3 * D1; i += blockDim.x) w[i] = bw[i];
    __syncthreads();

    int warp = (blockIdx.x * blockDim.x + threadIdx.x) >> 5;
    int lane = threadIdx.x & 31;
    if (warp >= n) return;
    int s0 = g_rowptr[warp], s1 = g_rowptr[warp + 1];

    const float* prow = g_p1 + (size_t)warp * NTOT1;
    float4 qa = *(const float4*)(prow + lane * 8);
    float4 qb = *(const float4*)(prow + lane * 8 + 4);
    float q[8] = { qa.x, qa.y, qa.z, qa.w, qb.x, qb.y, qb.z, qb.w };

    float a[8] = {0, 0, 0, 0, 0, 0, 0, 0};
    float asum = 0.f;
    int s = s0;
    for (; s + 1 < s1; s += 2) {
        int src0 = g_csrsrc[s], src1 = g_csrsrc[s + 1];
        const __half* kv0 = g_kv1 + (size_t)src0 * 512;
        const __half* kv1 = g_kv1 + (size_t)src1 * 512;
        uint4 kr0 = *(const uint4*)(kv0 + lane * 8);
        uint4 kr1 = *(const uint4*)(kv1 + lane * 8);
        uint4 vr0 = *(const uint4*)(kv0 + 256 + lane * 8);
        uint4 vr1 = *(const uint4*)(kv1 + 256 + lane * 8);
        const __half2* k0h = (const __half2*)&kr0;
        const __half2* k1h = (const __half2*)&kr1;
        const __half2* v0h = (const __half2*)&vr0;
        const __half2* v1h = (const __half2*)&vr1;

        float p0 = 0.f, p1 = 0.f;
        #pragma unroll
        for (int j = 0; j < 4; j++) {
            float2 f0 = __half22float2(k0h[j]);
            float2 f1 = __half22float2(k1h[j]);
            p0 = fmaf(q[2*j], f0.x, fmaf(q[2*j+1], f0.y, p0));
            p1 = fmaf(q[2*j], f1.x, fmaf(q[2*j+1], f1.y, p1));
        }
        p0 += __shfl_xor_sync(0xffffffffu, p0, 1);
        p0 += __shfl_xor_sync(0xffffffffu, p0, 2);
        p1 += __shfl_xor_sync(0xffffffffu, p1, 1);
        p1 += __shfl_xor_sync(0xffffffffu, p1, 2);
        float e0 = expf(p0), e1 = expf(p1);   // q pre-scaled by 1/sqrt(32)
        asum += e0 + e1;
        #pragma unroll
        for (int j = 0; j < 4; j++) {
            float2 f0 = __half22float2(v0h[j]);
            float2 f1 = __half22float2(v1h[j]);
            a[2*j]   = fmaf(e0, f0.x, fmaf(e1, f1.x, a[2*j]));
            a[2*j+1] = fmaf(e0, f0.y, fmaf(e1, f1.y, a[2*j+1]));
        }
    }
    if (s < s1) {
        int src = g_csrsrc[s];
        const __half* kv = g_kv1 + (size_t)src * 512;
        uint4 kr = *(const uint4*)(kv + lane * 8);
        uint4 vr = *(const uint4*)(kv + 256 + lane * 8);
        const __half2* kh = (const __half2*)&kr;
        const __half2* vh = (const __half2*)&vr;
        float p = 0.f;
        #pragma unroll
        for (int j = 0; j < 4; j++) {
            float2 f = __half22float2(kh[j]);
            p = fmaf(q[2*j], f.x, fmaf(q[2*j+1], f.y, p));
        }
        p += __shfl_xor_sync(0xffffffffu, p, 1);
        p += __shfl_xor_sync(0xffffffffu, p, 2);
        float e = expf(p);
        asum += e;
        #pragma unroll
        for (int j = 0; j < 4; j++) {
            float2 f = __half22float2(vh[j]);
            a[2*j]   = fmaf(e, f.x, a[2*j]);
            a[2*j+1] = fmaf(e, f.y, a[2*j+1]);
        }
    }
    float inv = (s1 > s0) ? 1.0f / asum : 0.f;
    float o[8];
    #pragma unroll
    for (int j = 0; j < 8; j++) o[j] = a[j] * inv;

    float4 sa = *(const float4*)(prow + 768 + lane * 8);
    float4 sbv = *(const float4*)(prow + 768 + lane * 8 + 4);
    float sk[8] = { sa.x, sa.y, sa.z, sa.w, sbv.x, sbv.y, sbv.z, sbv.w };

    float g = 0.f;
    #pragma unroll
    for (int j = 0; j < 8; j++) {
        int ccol = lane * 8 + j;
        g += o[j] * w[ccol] + sk[j] * w[D1 + ccol] + (o[j] - sk[j]) * w[2 * D1 + ccol];
    }
    #pragma unroll
    for (int off = 16; off >= 1; off >>= 1) g += __shfl_xor_sync(0xffffffffu, g, off);
    float beta = 1.0f / (1.0f + expf(-g));

    __nv_bfloat162 ph[4], pl[4];
    #pragma unroll
    for (int j = 0; j < 4; j++) {
        float v0 = beta * sk[2*j]   + (1.0f - beta) * o[2*j];
        float v1 = beta * sk[2*j+1] + (1.0f - beta) * o[2*j+1];
        v0 = (v0 > 0.f) ? v0 : (expf(v0) - 1.0f);   // ELU
        v1 = (v1 > 0.f) ? v1 : (expf(v1) - 1.0f);
        __nv_bfloat16 h0 = __float2bfloat16(v0), h1 = __float2bfloat16(v1);
        ph[j] = __halves2bfloat162(h0, h1);
        pl[j] = __halves2bfloat162(__float2bfloat16(v0 - __bfloat162float(h0)),
                                   __float2bfloat16(v1 - __bfloat162float(h1)));
    }
    *(uint4*)&g_hhi[(size_t)warp * D1 + lane * 8] = *(uint4*)ph;
    *(uint4*)&g_hlo[(size_t)warp * D1 + lane * 8] = *(uint4*)pl;
}

// ---------------- fused layer-2 edge pass (unrolled x2 gather) ----------------
__global__ void __launch_bounds__(256) k_edge2(const float* __restrict__ bw,
                                               float* __restrict__ out, int n)
{
    __shared__ float w[3 * NOUT];
    for (int i = threadIdx.x; i < 3 * NOUT; i += blockDim.x) w[i] = bw[i];
    __syncthreads();

    int warp = (blockIdx.x * blockDim.x + threadIdx.x) >> 5;
    int lane = threadIdx.x & 31;
    if (warp >= n) return;
    int s0 = g_rowptr[warp], s1 = g_rowptr[warp + 1];

    const float* prow = g_p2 + (size_t)warp * NTOT2;
    float q0 = 0.f, q1 = 0.f;
    if (lane < 20) {
        float2 qq = *(const float2*)(prow + lane * 2);
        q0 = qq.x; q1 = qq.y;
    }
    float acc0 = 0.f, acc1 = 0.f, asum = 0.f;
    int s = s0;
    for (; s + 1 < s1; s += 2) {
        int src0 = g_csrsrc[s], src1 = g_csrsrc[s + 1];
        const float* b0p = g_p2 + (size_t)src0 * NTOT2;
        const float* b1p = g_p2 + (size_t)src1 * NTOT2;
        float p0 = 0.f, p1 = 0.f;
        float v00 = 0.f, v01 = 0.f, v10 = 0.f, v11 = 0.f;
        if (lane < 20) {
            float2 k0 = *(const float2*)(b0p + 40 + lane * 2);
            float2 k1 = *(const float2*)(b1p + 40 + lane * 2);
            float2 w0 = *(const float2*)(b0p + 80 + lane * 2);
            float2 w1 = *(const float2*)(b1p + 80 + lane * 2);
            p0 = q0 * k0.x + q1 * k0.y;
            p1 = q0 * k1.x + q1 * k1.y;
            v00 = w0.x; v01 = w0.y; v10 = w1.x; v11 = w1.y;
        }
        #pragma unroll
        for (int off = 16; off >= 1; off >>= 1) {
            p0 += __shfl_xor_sync(0xffffffffu, p0, off);
            p1 += __shfl_xor_sync(0xffffffffu, p1, off);
        }
        float e0 = expf(p0), e1 = expf(p1);   // q pre-scaled by 1/sqrt(40)
        asum += e0 + e1;
        acc0 = fmaf(e0, v00, acc0); acc1 = fmaf(e0, v01, acc1);
        acc0 = fmaf(e1, v10, acc0); acc1 = fmaf(e1, v11, acc1);
    }
    if (s < s1) {
        int src = g_csrsrc[s];
        const float* base = g_p2 + (size_t)src * NTOT2;
        float p = 0.f, v0 = 0.f, v1 = 0.f;
        if (lane < 20) {
            float2 kk = *(const float2*)(base + 40 + lane * 2);
            p = q0 * kk.x + q1 * kk.y;
            float2 vv = *(const float2*)(base + 80 + lane * 2);
            v0 = vv.x; v1 = vv.y;
        }
        #pragma unroll
        for (int off = 16; off >= 1; off >>= 1) p += __shfl_xor_sync(0xffffffffu, p, off);
        float e = expf(p);
        asum += e;
        acc0 = fmaf(e, v0, acc0);
        acc1 = fmaf(e, v1, acc1);
    }
    float inv = (s1 > s0) ? 1.0f / asum : 0.f;
    float o0 = acc0 * inv, o1 = acc1 * inv;

    float sk0 = 0.f, sk1 = 0.f, g = 0.f;
    if (lane < 20) {
        float2 ss = *(const float2*)(prow + 120 + lane * 2);
        sk0 = ss.x; sk1 = ss.y;
        int ccol = lane * 2;
        g = o0 * w[ccol]     + sk0 * w[NOUT + ccol]     + (o0 - sk0) * w[2 * NOUT + ccol]
          + o1 * w[ccol + 1] + sk1 * w[NOUT + ccol + 1] + (o1 - sk1) * w[2 * NOUT + ccol + 1];
    }
    #pragma unroll
    for (int off = 16; off >= 1; off >>= 1) g += __shfl_xor_sync(0xffffffffu, g, off);
    float beta = 1.0f / (1.0f + expf(-g));
    if (lane < 20) {
        float r0 = beta * sk0 + (1.0f - beta) * o0;
        float r1 = beta * sk1 + (1.0f - beta) * o1;
        *(float2*)(out + (size_t)warp * NOUT + lane * 2) = make_float2(r0, r1);
    }
}

// ---------------- launch ----------------
extern "C" void kernel_launch(void* const* d_in, const int* in_sizes, int n_in,
                              void* d_out, int out_size)
{
    const float* x = (const float*)d_in[0];
    const void* ei = d_in[1];
    const float* q1w = (const float*)d_in[2];
    const float* q1b = (const float*)d_in[3];
    const float* k1w = (const float*)d_in[4];
    const float* k1b = (const float*)d_in[5];
    const float* v1w = (const float*)d_in[6];
    const float* v1b = (const float*)d_in[7];
    const float* s1w = (const float*)d_in[8];
    const float* s1b = (const float*)d_in[9];
    const float* b1w = (const float*)d_in[10];
    const float* q2w = (const float*)d_in[11];
    const float* q2b = (const float*)d_in[12];
    const float* k2w = (const float*)d_in[13];
    const float* k2b = (const float*)d_in[14];
    const float* v2w = (const float*)d_in[15];
    const float* v2b = (const float*)d_in[16];
    const float* s2w = (const float*)d_in[17];
    const float* s2b = (const float*)d_in[18];
    const float* b2w = (const float*)d_in[19];
    float* out = (float*)d_out;

    const int n = in_sizes[0] / FIN;   // 50000
    const int e = in_sizes[1] / 2;     // 800000

    float* d_p1; cudaGetSymbolAddress((void**)&d_p1, g_p1);
    float* d_p2; cudaGetSymbolAddress((void**)&d_p2, g_p2);
    __nv_bfloat16 *d_xhi, *d_xlo, *d_hhi, *d_hlo, *d_w1hi, *d_w1lo, *d_w2hi, *d_w2lo;
    cudaGetSymbolAddress((void**)&d_xhi, g_xhi);
    cudaGetSymbolAddress((void**)&d_xlo, g_xlo);
    cudaGetSymbolAddress((void**)&d_hhi, g_hhi);
    cudaGetSymbolAddress((void**)&d_hlo, g_hlo);
    cudaGetSymbolAddress((void**)&d_w1hi, g_w1hi);
    cudaGetSymbolAddress((void**)&d_w1lo, g_w1lo);
    cudaGetSymbolAddress((void**)&d_w2hi, g_w2hi);
    cudaGetSymbolAddress((void**)&d_w2lo, g_w2lo);
    float *d_b1, *d_b2;
    cudaGetSymbolAddress((void**)&d_b1, g_b1);
    cudaGetSymbolAddress((void**)&d_b2, g_b2);

    static cudaStream_t s2 = 0;
    static cudaEvent_t evA = 0, evB = 0;
    if (!s2)  cudaStreamCreateWithFlags(&s2, cudaStreamNonBlocking);
    if (!evA) cudaEventCreateWithFlags(&evA, cudaEventDisableTiming);
    if (!evB) cudaEventCreateWithFlags(&evB, cudaEventDisableTiming);

    const int GSMEM = 4 * TILEB * 2;  // 73728 B (2 CTA/SM; L1D keeps ~80KB)
    cudaFuncSetAttribute((const void*)k_mma2<2, 1>, cudaFuncAttributeMaxDynamicSharedMemorySize, GSMEM);
    cudaFuncSetAttribute((const void*)k_mma2<4, 0>, cudaFuncAttributeMaxDynamicSharedMemorySize, GSMEM);

    const int mblocks = cdiv(n, 128);
    const int nodeBlocks = cdiv(n * 32, 256);

    // fork immediately: CSR chain (no deps on main-stream work)
    cudaEventRecord(evA, 0);
    cudaStreamWaitEvent(s2, evA, 0);

    k_init<<<cdiv(n, 256), 256, 0, s2>>>(n);                       // s2
    k_detect<<<cdiv(e, 256), 256, 0, s2>>>((const int*)ei, e);     // s2
    const int packTotal = NTOT1 * FIN + N2P * D1 + NTOT1 + N2P;
    k_packw<<<cdiv(packTotal, 256), 256>>>(                        // main
        q1w, k1w, v1w, s1w, q1b, k1b, v1b, s1b,
        q2w, k2w, v2w, s2w, q2b, k2b, v2b, s2b);
    k_split<<<cdiv(n * FIN / 4, 256), 256>>>(x, d_xhi, d_xlo, n * FIN / 4);  // main
    k_mma2<2, 1><<<dim3(NTOT1 / 128, mblocks), 256, GSMEM>>>(      // main
        d_xhi, d_xlo, d_w1hi, d_w1lo, d_b1, d_p1, n, NTOT1, NTOT1);

    k_convhist<<<cdiv(e, 256), 256, 0, s2>>>(ei, e);               // s2
    k_scan<<<1, 1024, 0, s2>>>(n);                                 // s2
    k_scatter<<<cdiv(e, 256), 256, 0, s2>>>(e);                    // s2
    cudaEventRecord(evB, s2);

    // join: edge1 needs gemm1 (main) + CSR (s2)
    cudaStreamWaitEvent(0, evB, 0);
    k_edge1<<<nodeBlocks, 256>>>(b1w, n);

    // ---- layer 2 ----
    k_mma2<4, 0><<<dim3(N2P / 128, mblocks), 256, GSMEM>>>(
        d_hhi, d_hlo, d_w2hi, d_w2lo, d_b2, d_p2, n, NTOT2, NTOT2);
    k_edge2<<<nodeBlocks, 256>>>(b2w, out, n);
}